// round 9
// baseline (speedup 1.0000x reference)
#include <cuda_runtime.h>
#include <cuda_bf16.h>
#include <cstdint>

// ---------------------------------------------------------------------------
// GCN layer: out = relu( A_coo @ ((x .* mask) @ W) )
//   side stream : W -> per-lane bf16 hi/lo fragment images, then mma.sync
//                 bf16-split GEMM (warp = 16 rows x 128 cols, A read once)
//   main stream : zero -> hist -> fused decoupled-lookback scan -> scatter
//   join        : per-row warp aggregation (coalesced metadata + shfl,
//                 all gathers issued back-to-back) + relu
// ---------------------------------------------------------------------------

#define NMAX 100000
#define EMAX 1600000
#define D_IN 256
#define D_OUT 128
#define SCAN_B 1024
#define NBLK_MAX 128

__device__ float g_h[(size_t)NMAX * D_OUT];
__device__ int   g_counts[NMAX + 1];
__device__ int   g_offsets[NMAX + 1];
__device__ int   g_cursor[NMAX];
__device__ int2  g_csr[EMAX];            // (col, weight-bits) interleaved
__device__ int   g_pub[NBLK_MAX];        // lookback: bit30 = ready, low = aggregate
// Pre-swizzled B fragments: [ks][j][lane] -> (bh0, bh1, bl0, bl1)
__device__ uint4 g_wfrag[16 * 16 * 32];

// ---------------- bf16 split helpers ----------------
__device__ __forceinline__ uint32_t pack_bf16x2(float lo_elem, float hi_elem) {
    uint32_t r;
    asm("cvt.rn.bf16x2.f32 %0, %1, %2;" : "=r"(r) : "f"(hi_elem), "f"(lo_elem));
    return r;
}
__device__ __forceinline__ float bf_lo_f32(uint32_t p) { return __uint_as_float(p << 16); }
__device__ __forceinline__ float bf_hi_f32(uint32_t p) { return __uint_as_float(p & 0xFFFF0000u); }

// mma.sync m16n8k16 bf16 (row.col), fp32 accumulate
__device__ __forceinline__ void mma16816(float* d,
                                         uint32_t a0, uint32_t a1, uint32_t a2, uint32_t a3,
                                         uint32_t b0, uint32_t b1) {
    asm volatile(
        "mma.sync.aligned.m16n8k16.row.col.f32.bf16.bf16.f32 "
        "{%0,%1,%2,%3}, {%4,%5,%6,%7}, {%8,%9}, {%0,%1,%2,%3};"
        : "+f"(d[0]), "+f"(d[1]), "+f"(d[2]), "+f"(d[3])
        : "r"(a0), "r"(a1), "r"(a2), "r"(a3), "r"(b0), "r"(b1));
}

// ---------------- W -> per-lane fragment images ----------------
__global__ __launch_bounds__(256)
void wconv_kernel(const float* __restrict__ W)
{
    const int idx  = blockIdx.x * 256 + threadIdx.x;   // 0..8191
    const int lane = idx & 31;
    const int j    = (idx >> 5) & 15;
    const int ks   = idx >> 9;
    const int lq   = lane >> 2;
    const int lr   = lane & 3;
    const int n    = j * 8 + lq;
    const int k    = ks * 16 + lr * 2;

    const float w0 = W[(size_t)k       * D_OUT + n];
    const float w1 = W[(size_t)(k + 1) * D_OUT + n];
    const float w2 = W[(size_t)(k + 8) * D_OUT + n];
    const float w3 = W[(size_t)(k + 9) * D_OUT + n];

    const uint32_t bh0 = pack_bf16x2(w0, w1);
    const uint32_t bh1 = pack_bf16x2(w2, w3);
    const uint32_t bl0 = pack_bf16x2(w0 - bf_lo_f32(bh0), w1 - bf_hi_f32(bh0));
    const uint32_t bl1 = pack_bf16x2(w2 - bf_lo_f32(bh1), w3 - bf_hi_f32(bh1));
    g_wfrag[idx] = make_uint4(bh0, bh1, bl0, bl1);
}

// ---------------- GEMM: g_h = (x.*mask) @ W via mma.sync bf16 split --------
__global__ __launch_bounds__(256)
void gemm_mma_kernel(const float* __restrict__ x, const float* __restrict__ mask,
                     int M)
{
    const int wid  = threadIdx.x >> 5;
    const int lane = threadIdx.x & 31;
    const int lq   = lane >> 2;
    const int lr   = lane & 3;
    const int rowb = blockIdx.x * 128 + wid * 16;

    const int r0 = rowb + lq;
    const int r1 = rowb + 8 + lq;
    const int g0 = (r0 < M) ? r0 : (M - 1);
    const int g1 = (r1 < M) ? r1 : (M - 1);
    const float* __restrict__ x0 = &x[(size_t)g0 * D_IN];
    const float* __restrict__ m0 = &mask[(size_t)g0 * D_IN];
    const float* __restrict__ x1 = &x[(size_t)g1 * D_IN];
    const float* __restrict__ m1 = &mask[(size_t)g1 * D_IN];

    float acc[16][4];
#pragma unroll
    for (int j = 0; j < 16; j++)
#pragma unroll
        for (int q = 0; q < 4; q++) acc[j][q] = 0.f;

#pragma unroll 1
    for (int ks = 0; ks < 16; ks++) {
        const int kc = ks * 16 + lr * 2;

        const float2 xa = *(const float2*)&x0[kc];
        const float2 ma = *(const float2*)&m0[kc];
        const float2 xb = *(const float2*)&x0[kc + 8];
        const float2 mb = *(const float2*)&m0[kc + 8];
        const float2 xc = *(const float2*)&x1[kc];
        const float2 mc = *(const float2*)&m1[kc];
        const float2 xd = *(const float2*)&x1[kc + 8];
        const float2 md = *(const float2*)&m1[kc + 8];

        const float pa0 = xa.x * ma.x, pa1 = xa.y * ma.y;
        const float pb0 = xb.x * mb.x, pb1 = xb.y * mb.y;
        const float pc0 = xc.x * mc.x, pc1 = xc.y * mc.y;
        const float pd0 = xd.x * md.x, pd1 = xd.y * md.y;

        const uint32_t ah0 = pack_bf16x2(pa0, pa1);
        const uint32_t ah1 = pack_bf16x2(pc0, pc1);
        const uint32_t ah2 = pack_bf16x2(pb0, pb1);
        const uint32_t ah3 = pack_bf16x2(pd0, pd1);
        const uint32_t al0 = pack_bf16x2(pa0 - bf_lo_f32(ah0), pa1 - bf_hi_f32(ah0));
        const uint32_t al1 = pack_bf16x2(pc0 - bf_lo_f32(ah1), pc1 - bf_hi_f32(ah1));
        const uint32_t al2 = pack_bf16x2(pb0 - bf_lo_f32(ah2), pb1 - bf_hi_f32(ah2));
        const uint32_t al3 = pack_bf16x2(pd0 - bf_lo_f32(ah3), pd1 - bf_hi_f32(ah3));

        const uint4* __restrict__ wf = &g_wfrag[ks * 512 + lane];
#pragma unroll
        for (int j = 0; j < 16; j++) {
            const uint4 f = wf[j * 32];
            mma16816(acc[j], ah0, ah1, ah2, ah3, f.x, f.y);
            mma16816(acc[j], ah0, ah1, ah2, ah3, f.z, f.w);
            mma16816(acc[j], al0, al1, al2, al3, f.x, f.y);
        }
    }

#pragma unroll
    for (int j = 0; j < 16; j++) {
        const int c = j * 8 + lr * 2;
        if (r0 < M)
            *(float2*)&g_h[(size_t)r0 * D_OUT + c] = make_float2(acc[j][0], acc[j][1]);
        if (r1 < M)
            *(float2*)&g_h[(size_t)r1 * D_OUT + c] = make_float2(acc[j][2], acc[j][3]);
    }
}

// ---------------- CSR build ----------------
__global__ void zero_kernel(int n)
{
    int i = blockIdx.x * blockDim.x + threadIdx.x;
    if (i <= n) g_counts[i] = 0;
    if (i < NBLK_MAX) g_pub[i] = 0;
}

__global__ void hist_kernel(const int* __restrict__ erow, int E)
{
    int e = blockIdx.x * blockDim.x + threadIdx.x;
    if (e < E) atomicAdd(&g_counts[erow[e]], 1);
}

__device__ __forceinline__ int block_scan_incl(int v)
{
    __shared__ int ws[32];
    const int lane = threadIdx.x & 31;
    const int w    = threadIdx.x >> 5;
#pragma unroll
    for (int o = 1; o < 32; o <<= 1) {
        int u = __shfl_up_sync(0xFFFFFFFFu, v, o);
        if (lane >= o) v += u;
    }
    if (lane == 31) ws[w] = v;
    __syncthreads();
    if (w == 0) {
        int s = ws[lane];
#pragma unroll
        for (int o = 1; o < 32; o <<= 1) {
            int u = __shfl_up_sync(0xFFFFFFFFu, s, o);
            if (lane >= o) s += u;
        }
        ws[lane] = s;
    }
    __syncthreads();
    return v + ((w > 0) ? ws[w - 1] : 0);
}

// Fused decoupled-lookback scan: counts -> offsets (+cursor, +total).
__global__ __launch_bounds__(SCAN_B)
void scan_fused_kernel(int n, int nblk)
{
    const int b = blockIdx.x;
    const int t = threadIdx.x;
    const int i = b * SCAN_B + t;
    const int v = (i < n) ? g_counts[i] : 0;
    const int incl = block_scan_incl(v);

    __shared__ int s_base;
    __shared__ int s_pred[128];

    if (t == SCAN_B - 1)
        atomicExch(&g_pub[b], incl | 0x40000000);

    if (t < 128) {
        int val = 0;
        if (t < b) {
            int s;
            do { s = *(volatile int*)&g_pub[t]; } while (!(s & 0x40000000));
            val = s & 0x3FFFFFFF;
        }
        s_pred[t] = val;
    }
    __syncthreads();
    if (t < 32) {
        int s = s_pred[t] + s_pred[t + 32] + s_pred[t + 64] + s_pred[t + 96];
#pragma unroll
        for (int o = 16; o; o >>= 1) s += __shfl_down_sync(0xFFFFFFFFu, s, o);
        if (t == 0) s_base = s;
    }
    __syncthreads();
    const int base = s_base;

    if (i < n) {
        const int o = base + incl - v;
        g_offsets[i] = o;
        g_cursor[i]  = o;
    }
    if (b == nblk - 1 && t == SCAN_B - 1)
        g_offsets[n] = base + incl;
}

__global__ void scatter_kernel(const int* __restrict__ erow,
                               const int* __restrict__ ecol,
                               const float* __restrict__ ew, int E)
{
    int e = blockIdx.x * blockDim.x + threadIdx.x;
    if (e < E) {
        int p = atomicAdd(&g_cursor[erow[e]], 1);
        g_csr[p] = make_int2(ecol[e], __float_as_int(ew[e]));
    }
}

// ---------------- aggregation: coalesced metadata + shfl broadcast ---------
// One warp per row. Lane i prefetches edge metadata (beg+i) with ONE coalesced
// load per 32-edge chunk; (col, w) broadcast via shfl so every gather issues
// without waiting on a memory-dependent metadata load. MLP ~ row degree.
__global__ __launch_bounds__(256)
void agg_kernel(float* __restrict__ out, int N)
{
    const int wid  = (blockIdx.x * blockDim.x + threadIdx.x) >> 5;
    const int lane = threadIdx.x & 31;
    if (wid >= N) return;

    const int beg = g_offsets[wid];
    const int end = g_offsets[wid + 1];
    const float4* __restrict__ h4 = (const float4*)g_h;

    float4 a0 = make_float4(0.f, 0.f, 0.f, 0.f);
    float4 a1 = make_float4(0.f, 0.f, 0.f, 0.f);

    for (int base = beg; base < end; base += 32) {
        const int cnt = min(32, end - base);
        int2 meta = make_int2(0, 0);
        if (base + lane < end) meta = g_csr[base + lane];

        int j = 0;
        for (; j + 2 <= cnt; j += 2) {
            const int   c0 = __shfl_sync(0xFFFFFFFFu, meta.x, j);
            const int   w0i = __shfl_sync(0xFFFFFFFFu, meta.y, j);
            const int   c1 = __shfl_sync(0xFFFFFFFFu, meta.x, j + 1);
            const int   w1i = __shfl_sync(0xFFFFFFFFu, meta.y, j + 1);
            const float4 v0 = h4[(size_t)c0 * 32 + lane];
            const float4 v1 = h4[(size_t)c1 * 32 + lane];
            const float w0 = __int_as_float(w0i);
            const float w1 = __int_as_float(w1i);
            a0.x = fmaf(w0, v0.x, a0.x); a0.y = fmaf(w0, v0.y, a0.y);
            a0.z = fmaf(w0, v0.z, a0.z); a0.w = fmaf(w0, v0.w, a0.w);
            a1.x = fmaf(w1, v1.x, a1.x); a1.y = fmaf(w1, v1.y, a1.y);
            a1.z = fmaf(w1, v1.z, a1.z); a1.w = fmaf(w1, v1.w, a1.w);
        }
        if (j < cnt) {
            const int   c0 = __shfl_sync(0xFFFFFFFFu, meta.x, j);
            const int   w0i = __shfl_sync(0xFFFFFFFFu, meta.y, j);
            const float4 v0 = h4[(size_t)c0 * 32 + lane];
            const float w0 = __int_as_float(w0i);
            a0.x = fmaf(w0, v0.x, a0.x); a0.y = fmaf(w0, v0.y, a0.y);
            a0.z = fmaf(w0, v0.z, a0.z); a0.w = fmaf(w0, v0.w, a0.w);
        }
    }

    float4 r;
    r.x = fmaxf(a0.x + a1.x, 0.f);
    r.y = fmaxf(a0.y + a1.y, 0.f);
    r.z = fmaxf(a0.z + a1.z, 0.f);
    r.w = fmaxf(a0.w + a1.w, 0.f);
    ((float4*)out)[(size_t)wid * 32 + lane] = r;
}

// ---------------------------------------------------------------------------
extern "C" void kernel_launch(void* const* d_in, const int* in_sizes, int n_in,
                              void* d_out, int out_size)
{
    const float* x    = (const float*)d_in[0];
    const float* mask = (const float*)d_in[1];
    const float* W    = (const float*)d_in[2];
    const int*   erow = (const int*)d_in[3];
    const int*   ecol = (const int*)d_in[4];
    const float* ew   = (const float*)d_in[5];
    float* out = (float*)d_out;

    const int M = in_sizes[0] / D_IN;   // 100000
    const int E = in_sizes[3];          // 1600000
    const int nblk = (M + SCAN_B - 1) / SCAN_B;   // 98

    static cudaStream_t s_side = nullptr;
    static cudaEvent_t  s_fork = nullptr, s_join = nullptr;
    if (s_side == nullptr) {
        cudaStreamCreateWithFlags(&s_side, cudaStreamNonBlocking);
        cudaEventCreateWithFlags(&s_fork, cudaEventDisableTiming);
        cudaEventCreateWithFlags(&s_join, cudaEventDisableTiming);
    }

    // fork: side stream converts W then runs the tensor GEMM
    cudaEventRecord(s_fork, 0);
    cudaStreamWaitEvent(s_side, s_fork, 0);
    wconv_kernel<<<32, 256, 0, s_side>>>(W);
    gemm_mma_kernel<<<(M + 127) / 128, 256, 0, s_side>>>(x, mask, M);
    cudaEventRecord(s_join, s_side);

    // main stream: CSR build
    zero_kernel<<<(M + 256) / 256, 256>>>(M);
    hist_kernel<<<(E + 255) / 256, 256>>>(erow, E);
    scan_fused_kernel<<<nblk, SCAN_B>>>(M, nblk);
    scatter_kernel<<<(E + 255) / 256, 256>>>(erow, ecol, ew, E);

    // join, then aggregate
    cudaStreamWaitEvent(0, s_join, 0);
    agg_kernel<<<((size_t)M * 32 + 255) / 256, 256>>>(out, M);
}

// round 10
// speedup vs baseline: 1.1073x; 1.1073x over previous
#include <cuda_runtime.h>
#include <cuda_bf16.h>
#include <cstdint>

// ---------------------------------------------------------------------------
// GCN layer: out = relu( A_coo @ ((x .* mask) @ W) )
//   side stream : W -> per-lane bf16 hi/lo fragment images, then mma.sync
//                 bf16-split GEMM (warp = 16 rows x 128 cols, A read once)
//   main stream : zero -> hist -> fused decoupled-lookback scan -> scatter
//   join        : per-row warp aggregation + relu
// Cache policy: stream-once data (x, mask, edges, csr, out) uses evict-first
// (.cs) so g_h stays L2-resident for the gather phase.
// ---------------------------------------------------------------------------

#define NMAX 100000
#define EMAX 1600000
#define D_IN 256
#define D_OUT 128
#define SCAN_B 1024
#define NBLK_MAX 128

__device__ float g_h[(size_t)NMAX * D_OUT];
__device__ int   g_counts[NMAX + 1];
__device__ int   g_offsets[NMAX + 1];
__device__ int   g_cursor[NMAX];
__device__ int2  g_csr[EMAX];            // (col, weight-bits) interleaved
__device__ int   g_pub[NBLK_MAX];        // lookback: bit30 = ready, low = aggregate
// Pre-swizzled B fragments: [ks][j][lane] -> (bh0, bh1, bl0, bl1)
__device__ uint4 g_wfrag[16 * 16 * 32];

// ---------------- bf16 split helpers ----------------
__device__ __forceinline__ uint32_t pack_bf16x2(float lo_elem, float hi_elem) {
    uint32_t r;
    asm("cvt.rn.bf16x2.f32 %0, %1, %2;" : "=r"(r) : "f"(hi_elem), "f"(lo_elem));
    return r;
}
__device__ __forceinline__ float bf_lo_f32(uint32_t p) { return __uint_as_float(p << 16); }
__device__ __forceinline__ float bf_hi_f32(uint32_t p) { return __uint_as_float(p & 0xFFFF0000u); }

// mma.sync m16n8k16 bf16 (row.col), fp32 accumulate
__device__ __forceinline__ void mma16816(float* d,
                                         uint32_t a0, uint32_t a1, uint32_t a2, uint32_t a3,
                                         uint32_t b0, uint32_t b1) {
    asm volatile(
        "mma.sync.aligned.m16n8k16.row.col.f32.bf16.bf16.f32 "
        "{%0,%1,%2,%3}, {%4,%5,%6,%7}, {%8,%9}, {%0,%1,%2,%3};"
        : "+f"(d[0]), "+f"(d[1]), "+f"(d[2]), "+f"(d[3])
        : "r"(a0), "r"(a1), "r"(a2), "r"(a3), "r"(b0), "r"(b1));
}

// ---------------- W -> per-lane fragment images ----------------
__global__ __launch_bounds__(256)
void wconv_kernel(const float* __restrict__ W)
{
    const int idx  = blockIdx.x * 256 + threadIdx.x;   // 0..8191
    const int lane = idx & 31;
    const int j    = (idx >> 5) & 15;
    const int ks   = idx >> 9;
    const int lq   = lane >> 2;
    const int lr   = lane & 3;
    const int n    = j * 8 + lq;
    const int k    = ks * 16 + lr * 2;

    const float w0 = W[(size_t)k       * D_OUT + n];
    const float w1 = W[(size_t)(k + 1) * D_OUT + n];
    const float w2 = W[(size_t)(k + 8) * D_OUT + n];
    const float w3 = W[(size_t)(k + 9) * D_OUT + n];

    const uint32_t bh0 = pack_bf16x2(w0, w1);
    const uint32_t bh1 = pack_bf16x2(w2, w3);
    const uint32_t bl0 = pack_bf16x2(w0 - bf_lo_f32(bh0), w1 - bf_hi_f32(bh0));
    const uint32_t bl1 = pack_bf16x2(w2 - bf_lo_f32(bh1), w3 - bf_hi_f32(bh1));
    g_wfrag[idx] = make_uint4(bh0, bh1, bl0, bl1);
}

// ---------------- GEMM: g_h = (x.*mask) @ W via mma.sync bf16 split --------
__global__ __launch_bounds__(256)
void gemm_mma_kernel(const float* __restrict__ x, const float* __restrict__ mask,
                     int M)
{
    const int wid  = threadIdx.x >> 5;
    const int lane = threadIdx.x & 31;
    const int lq   = lane >> 2;
    const int lr   = lane & 3;
    const int rowb = blockIdx.x * 128 + wid * 16;

    const int r0 = rowb + lq;
    const int r1 = rowb + 8 + lq;
    const int g0 = (r0 < M) ? r0 : (M - 1);
    const int g1 = (r1 < M) ? r1 : (M - 1);
    const float* __restrict__ x0 = &x[(size_t)g0 * D_IN];
    const float* __restrict__ m0 = &mask[(size_t)g0 * D_IN];
    const float* __restrict__ x1 = &x[(size_t)g1 * D_IN];
    const float* __restrict__ m1 = &mask[(size_t)g1 * D_IN];

    float acc[16][4];
#pragma unroll
    for (int j = 0; j < 16; j++)
#pragma unroll
        for (int q = 0; q < 4; q++) acc[j][q] = 0.f;

#pragma unroll 1
    for (int ks = 0; ks < 16; ks++) {
        const int kc = ks * 16 + lr * 2;

        // stream-once reads: evict-first so g_h keeps L2
        const float2 xa = __ldcs((const float2*)&x0[kc]);
        const float2 ma = __ldcs((const float2*)&m0[kc]);
        const float2 xb = __ldcs((const float2*)&x0[kc + 8]);
        const float2 mb = __ldcs((const float2*)&m0[kc + 8]);
        const float2 xc = __ldcs((const float2*)&x1[kc]);
        const float2 mc = __ldcs((const float2*)&m1[kc]);
        const float2 xd = __ldcs((const float2*)&x1[kc + 8]);
        const float2 md = __ldcs((const float2*)&m1[kc + 8]);

        const float pa0 = xa.x * ma.x, pa1 = xa.y * ma.y;
        const float pb0 = xb.x * mb.x, pb1 = xb.y * mb.y;
        const float pc0 = xc.x * mc.x, pc1 = xc.y * mc.y;
        const float pd0 = xd.x * md.x, pd1 = xd.y * md.y;

        const uint32_t ah0 = pack_bf16x2(pa0, pa1);
        const uint32_t ah1 = pack_bf16x2(pc0, pc1);
        const uint32_t ah2 = pack_bf16x2(pb0, pb1);
        const uint32_t ah3 = pack_bf16x2(pd0, pd1);
        const uint32_t al0 = pack_bf16x2(pa0 - bf_lo_f32(ah0), pa1 - bf_hi_f32(ah0));
        const uint32_t al1 = pack_bf16x2(pc0 - bf_lo_f32(ah1), pc1 - bf_hi_f32(ah1));
        const uint32_t al2 = pack_bf16x2(pb0 - bf_lo_f32(ah2), pb1 - bf_hi_f32(ah2));
        const uint32_t al3 = pack_bf16x2(pd0 - bf_lo_f32(ah3), pd1 - bf_hi_f32(ah3));

        const uint4* __restrict__ wf = &g_wfrag[ks * 512 + lane];
#pragma unroll
        for (int j = 0; j < 16; j++) {
            const uint4 f = wf[j * 32];
            mma16816(acc[j], ah0, ah1, ah2, ah3, f.x, f.y);
            mma16816(acc[j], ah0, ah1, ah2, ah3, f.z, f.w);
            mma16816(acc[j], al0, al1, al2, al3, f.x, f.y);
        }
    }

#pragma unroll
    for (int j = 0; j < 16; j++) {
        const int c = j * 8 + lr * 2;
        if (r0 < M)
            *(float2*)&g_h[(size_t)r0 * D_OUT + c] = make_float2(acc[j][0], acc[j][1]);
        if (r1 < M)
            *(float2*)&g_h[(size_t)r1 * D_OUT + c] = make_float2(acc[j][2], acc[j][3]);
    }
}

// ---------------- CSR build ----------------
__global__ void zero_kernel(int n)
{
    int i = blockIdx.x * blockDim.x + threadIdx.x;
    if (i <= n) g_counts[i] = 0;
    if (i < NBLK_MAX) g_pub[i] = 0;
}

__global__ void hist_kernel(const int* __restrict__ erow, int E)
{
    int e = blockIdx.x * blockDim.x + threadIdx.x;
    if (e < E) atomicAdd(&g_counts[__ldcs(&erow[e])], 1);
}

__device__ __forceinline__ int block_scan_incl(int v)
{
    __shared__ int ws[32];
    const int lane = threadIdx.x & 31;
    const int w    = threadIdx.x >> 5;
#pragma unroll
    for (int o = 1; o < 32; o <<= 1) {
        int u = __shfl_up_sync(0xFFFFFFFFu, v, o);
        if (lane >= o) v += u;
    }
    if (lane == 31) ws[w] = v;
    __syncthreads();
    if (w == 0) {
        int s = ws[lane];
#pragma unroll
        for (int o = 1; o < 32; o <<= 1) {
            int u = __shfl_up_sync(0xFFFFFFFFu, s, o);
            if (lane >= o) s += u;
        }
        ws[lane] = s;
    }
    __syncthreads();
    return v + ((w > 0) ? ws[w - 1] : 0);
}

// Fused decoupled-lookback scan: counts -> offsets (+cursor, +total).
__global__ __launch_bounds__(SCAN_B)
void scan_fused_kernel(int n, int nblk)
{
    const int b = blockIdx.x;
    const int t = threadIdx.x;
    const int i = b * SCAN_B + t;
    const int v = (i < n) ? g_counts[i] : 0;
    const int incl = block_scan_incl(v);

    __shared__ int s_base;
    __shared__ int s_pred[128];

    if (t == SCAN_B - 1)
        atomicExch(&g_pub[b], incl | 0x40000000);

    if (t < 128) {
        int val = 0;
        if (t < b) {
            int s;
            do { s = *(volatile int*)&g_pub[t]; } while (!(s & 0x40000000));
            val = s & 0x3FFFFFFF;
        }
        s_pred[t] = val;
    }
    __syncthreads();
    if (t < 32) {
        int s = s_pred[t] + s_pred[t + 32] + s_pred[t + 64] + s_pred[t + 96];
#pragma unroll
        for (int o = 16; o; o >>= 1) s += __shfl_down_sync(0xFFFFFFFFu, s, o);
        if (t == 0) s_base = s;
    }
    __syncthreads();
    const int base = s_base;

    if (i < n) {
        const int o = base + incl - v;
        g_offsets[i] = o;
        g_cursor[i]  = o;
    }
    if (b == nblk - 1 && t == SCAN_B - 1)
        g_offsets[n] = base + incl;
}

__global__ void scatter_kernel(const int* __restrict__ erow,
                               const int* __restrict__ ecol,
                               const float* __restrict__ ew, int E)
{
    int e = blockIdx.x * blockDim.x + threadIdx.x;
    if (e < E) {
        int p = atomicAdd(&g_cursor[__ldcs(&erow[e])], 1);
        g_csr[p] = make_int2(__ldcs(&ecol[e]), __float_as_int(__ldcs(&ew[e])));
    }
}

// ---------------- aggregation: one warp per row, 2-edge unroll -------------
__global__ __launch_bounds__(256)
void agg_kernel(float* __restrict__ out, int N)
{
    const int wid  = (blockIdx.x * blockDim.x + threadIdx.x) >> 5;
    const int lane = threadIdx.x & 31;
    if (wid >= N) return;

    const int beg = g_offsets[wid];
    const int end = g_offsets[wid + 1];
    const float4* __restrict__ h4 = (const float4*)g_h;

    float4 a0 = make_float4(0.f, 0.f, 0.f, 0.f);
    float4 a1 = make_float4(0.f, 0.f, 0.f, 0.f);

    int e = beg;
    for (; e + 2 <= end; e += 2) {
        const int2 m0 = __ldcs(&g_csr[e]);
        const int2 m1 = __ldcs(&g_csr[e + 1]);
        const float4 v0 = h4[(size_t)m0.x * 32 + lane];
        const float4 v1 = h4[(size_t)m1.x * 32 + lane];
        const float w0 = __int_as_float(m0.y);
        const float w1 = __int_as_float(m1.y);
        a0.x = fmaf(w0, v0.x, a0.x); a0.y = fmaf(w0, v0.y, a0.y);
        a0.z = fmaf(w0, v0.z, a0.z); a0.w = fmaf(w0, v0.w, a0.w);
        a1.x = fmaf(w1, v1.x, a1.x); a1.y = fmaf(w1, v1.y, a1.y);
        a1.z = fmaf(w1, v1.z, a1.z); a1.w = fmaf(w1, v1.w, a1.w);
    }
    if (e < end) {
        const int2 m0 = __ldcs(&g_csr[e]);
        const float w0 = __int_as_float(m0.y);
        const float4 v0 = h4[(size_t)m0.x * 32 + lane];
        a0.x = fmaf(w0, v0.x, a0.x); a0.y = fmaf(w0, v0.y, a0.y);
        a0.z = fmaf(w0, v0.z, a0.z); a0.w = fmaf(w0, v0.w, a0.w);
    }

    float4 r;
    r.x = fmaxf(a0.x + a1.x, 0.f);
    r.y = fmaxf(a0.y + a1.y, 0.f);
    r.z = fmaxf(a0.z + a1.z, 0.f);
    r.w = fmaxf(a0.w + a1.w, 0.f);
    // write-once output: evict-first, keep g_h resident
    __stcs(&((float4*)out)[(size_t)wid * 32 + lane], r);
}

// ---------------------------------------------------------------------------
extern "C" void kernel_launch(void* const* d_in, const int* in_sizes, int n_in,
                              void* d_out, int out_size)
{
    const float* x    = (const float*)d_in[0];
    const float* mask = (const float*)d_in[1];
    const float* W    = (const float*)d_in[2];
    const int*   erow = (const int*)d_in[3];
    const int*   ecol = (const int*)d_in[4];
    const float* ew   = (const float*)d_in[5];
    float* out = (float*)d_out;

    const int M = in_sizes[0] / D_IN;   // 100000
    const int E = in_sizes[3];          // 1600000
    const int nblk = (M + SCAN_B - 1) / SCAN_B;   // 98

    static cudaStream_t s_side = nullptr;
    static cudaEvent_t  s_fork = nullptr, s_join = nullptr;
    if (s_side == nullptr) {
        cudaStreamCreateWithFlags(&s_side, cudaStreamNonBlocking);
        cudaEventCreateWithFlags(&s_fork, cudaEventDisableTiming);
        cudaEventCreateWithFlags(&s_join, cudaEventDisableTiming);
    }

    // fork: side stream converts W then runs the tensor GEMM
    cudaEventRecord(s_fork, 0);
    cudaStreamWaitEvent(s_side, s_fork, 0);
    wconv_kernel<<<32, 256, 0, s_side>>>(W);
    gemm_mma_kernel<<<(M + 127) / 128, 256, 0, s_side>>>(x, mask, M);
    cudaEventRecord(s_join, s_side);

    // main stream: CSR build
    zero_kernel<<<(M + 256) / 256, 256>>>(M);
    hist_kernel<<<(E + 255) / 256, 256>>>(erow, E);
    scan_fused_kernel<<<nblk, SCAN_B>>>(M, nblk);
    scatter_kernel<<<(E + 255) / 256, 256>>>(erow, ecol, ew, E);

    // join, then aggregate
    cudaStreamWaitEvent(0, s_join, 0);
    agg_kernel<<<((size_t)M * 32 + 255) / 256, 256>>>(out, M);
}

// round 11
// speedup vs baseline: 1.2155x; 1.0977x over previous
#include <cuda_runtime.h>
#include <cuda_fp16.h>
#include <cuda_bf16.h>
#include <cstdint>

// ---------------------------------------------------------------------------
// GCN layer: out = relu( A_coo @ ((x .* mask) @ W) )
//   side stream : W -> per-lane bf16 hi/lo fragment images, then mma.sync
//                 bf16-split GEMM (fp32 accum) -> h stored as fp16
//   main stream : zero -> hist -> fused decoupled-lookback scan -> scatter
//   join        : per-row warp aggregation (fp16 h gather, fp32 accum) + relu
// Cache policy: stream-once data (x, mask, edges, csr, out) is evict-first
// (.cs); fp16 h (25.6 MB) stays L2-resident for the gather phase.
// ---------------------------------------------------------------------------

#define NMAX 100000
#define EMAX 1600000
#define D_IN 256
#define D_OUT 128
#define SCAN_B 1024
#define NBLK_MAX 128

__device__ uint32_t g_hh[(size_t)NMAX * (D_OUT / 2)];   // h as half2 pairs
__device__ int   g_counts[NMAX + 1];
__device__ int   g_offsets[NMAX + 1];
__device__ int   g_cursor[NMAX];
__device__ int2  g_csr[EMAX];            // (col, weight-bits) interleaved
__device__ int   g_pub[NBLK_MAX];        // lookback: bit30 = ready, low = aggregate
// Pre-swizzled B fragments: [ks][j][lane] -> (bh0, bh1, bl0, bl1)
__device__ uint4 g_wfrag[16 * 16 * 32];

// ---------------- bf16 split helpers ----------------
__device__ __forceinline__ uint32_t pack_bf16x2(float lo_elem, float hi_elem) {
    uint32_t r;
    asm("cvt.rn.bf16x2.f32 %0, %1, %2;" : "=r"(r) : "f"(hi_elem), "f"(lo_elem));
    return r;
}
__device__ __forceinline__ float bf_lo_f32(uint32_t p) { return __uint_as_float(p << 16); }
__device__ __forceinline__ float bf_hi_f32(uint32_t p) { return __uint_as_float(p & 0xFFFF0000u); }

// mma.sync m16n8k16 bf16 (row.col), fp32 accumulate
__device__ __forceinline__ void mma16816(float* d,
                                         uint32_t a0, uint32_t a1, uint32_t a2, uint32_t a3,
                                         uint32_t b0, uint32_t b1) {
    asm volatile(
        "mma.sync.aligned.m16n8k16.row.col.f32.bf16.bf16.f32 "
        "{%0,%1,%2,%3}, {%4,%5,%6,%7}, {%8,%9}, {%0,%1,%2,%3};"
        : "+f"(d[0]), "+f"(d[1]), "+f"(d[2]), "+f"(d[3])
        : "r"(a0), "r"(a1), "r"(a2), "r"(a3), "r"(b0), "r"(b1));
}

// ---------------- W -> per-lane fragment images ----------------
__global__ __launch_bounds__(256)
void wconv_kernel(const float* __restrict__ W)
{
    const int idx  = blockIdx.x * 256 + threadIdx.x;   // 0..8191
    const int lane = idx & 31;
    const int j    = (idx >> 5) & 15;
    const int ks   = idx >> 9;
    const int lq   = lane >> 2;
    const int lr   = lane & 3;
    const int n    = j * 8 + lq;
    const int k    = ks * 16 + lr * 2;

    const float w0 = W[(size_t)k       * D_OUT + n];
    const float w1 = W[(size_t)(k + 1) * D_OUT + n];
    const float w2 = W[(size_t)(k + 8) * D_OUT + n];
    const float w3 = W[(size_t)(k + 9) * D_OUT + n];

    const uint32_t bh0 = pack_bf16x2(w0, w1);
    const uint32_t bh1 = pack_bf16x2(w2, w3);
    const uint32_t bl0 = pack_bf16x2(w0 - bf_lo_f32(bh0), w1 - bf_hi_f32(bh0));
    const uint32_t bl1 = pack_bf16x2(w2 - bf_lo_f32(bh1), w3 - bf_hi_f32(bh1));
    g_wfrag[idx] = make_uint4(bh0, bh1, bl0, bl1);
}

// ---------------- GEMM: h = (x.*mask) @ W via mma.sync bf16 split ----------
__global__ __launch_bounds__(256)
void gemm_mma_kernel(const float* __restrict__ x, const float* __restrict__ mask,
                     int M)
{
    const int wid  = threadIdx.x >> 5;
    const int lane = threadIdx.x & 31;
    const int lq   = lane >> 2;
    const int lr   = lane & 3;
    const int rowb = blockIdx.x * 128 + wid * 16;

    const int r0 = rowb + lq;
    const int r1 = rowb + 8 + lq;
    const int g0 = (r0 < M) ? r0 : (M - 1);
    const int g1 = (r1 < M) ? r1 : (M - 1);
    const float* __restrict__ x0 = &x[(size_t)g0 * D_IN];
    const float* __restrict__ m0 = &mask[(size_t)g0 * D_IN];
    const float* __restrict__ x1 = &x[(size_t)g1 * D_IN];
    const float* __restrict__ m1 = &mask[(size_t)g1 * D_IN];

    float acc[16][4];
#pragma unroll
    for (int j = 0; j < 16; j++)
#pragma unroll
        for (int q = 0; q < 4; q++) acc[j][q] = 0.f;

#pragma unroll 1
    for (int ks = 0; ks < 16; ks++) {
        const int kc = ks * 16 + lr * 2;

        const float2 xa = __ldcs((const float2*)&x0[kc]);
        const float2 ma = __ldcs((const float2*)&m0[kc]);
        const float2 xb = __ldcs((const float2*)&x0[kc + 8]);
        const float2 mb = __ldcs((const float2*)&m0[kc + 8]);
        const float2 xc = __ldcs((const float2*)&x1[kc]);
        const float2 mc = __ldcs((const float2*)&m1[kc]);
        const float2 xd = __ldcs((const float2*)&x1[kc + 8]);
        const float2 md = __ldcs((const float2*)&m1[kc + 8]);

        const float pa0 = xa.x * ma.x, pa1 = xa.y * ma.y;
        const float pb0 = xb.x * mb.x, pb1 = xb.y * mb.y;
        const float pc0 = xc.x * mc.x, pc1 = xc.y * mc.y;
        const float pd0 = xd.x * md.x, pd1 = xd.y * md.y;

        const uint32_t ah0 = pack_bf16x2(pa0, pa1);
        const uint32_t ah1 = pack_bf16x2(pc0, pc1);
        const uint32_t ah2 = pack_bf16x2(pb0, pb1);
        const uint32_t ah3 = pack_bf16x2(pd0, pd1);
        const uint32_t al0 = pack_bf16x2(pa0 - bf_lo_f32(ah0), pa1 - bf_hi_f32(ah0));
        const uint32_t al1 = pack_bf16x2(pc0 - bf_lo_f32(ah1), pc1 - bf_hi_f32(ah1));
        const uint32_t al2 = pack_bf16x2(pb0 - bf_lo_f32(ah2), pb1 - bf_hi_f32(ah2));
        const uint32_t al3 = pack_bf16x2(pd0 - bf_lo_f32(ah3), pd1 - bf_hi_f32(ah3));

        const uint4* __restrict__ wf = &g_wfrag[ks * 512 + lane];
#pragma unroll
        for (int j = 0; j < 16; j++) {
            const uint4 f = wf[j * 32];
            mma16816(acc[j], ah0, ah1, ah2, ah3, f.x, f.y);
            mma16816(acc[j], ah0, ah1, ah2, ah3, f.z, f.w);
            mma16816(acc[j], al0, al1, al2, al3, f.x, f.y);
        }
    }

    // epilogue: cols (c, c+1) -> one half2 store per row
#pragma unroll
    for (int j = 0; j < 16; j++) {
        const int cpair = j * 4 + lr;        // half2 index = (j*8 + lr*2)/2
        if (r0 < M) {
            const __half2 h0 = __float22half2_rn(make_float2(acc[j][0], acc[j][1]));
            g_hh[(size_t)r0 * 64 + cpair] = *(const uint32_t*)&h0;
        }
        if (r1 < M) {
            const __half2 h1 = __float22half2_rn(make_float2(acc[j][2], acc[j][3]));
            g_hh[(size_t)r1 * 64 + cpair] = *(const uint32_t*)&h1;
        }
    }
}

// ---------------- CSR build ----------------
__global__ void zero_kernel(int n)
{
    int i = blockIdx.x * blockDim.x + threadIdx.x;
    if (i <= n) g_counts[i] = 0;
    if (i < NBLK_MAX) g_pub[i] = 0;
}

__global__ void hist_kernel(const int* __restrict__ erow, int E)
{
    int e = blockIdx.x * blockDim.x + threadIdx.x;
    if (e < E) atomicAdd(&g_counts[__ldcs(&erow[e])], 1);
}

__device__ __forceinline__ int block_scan_incl(int v)
{
    __shared__ int ws[32];
    const int lane = threadIdx.x & 31;
    const int w    = threadIdx.x >> 5;
#pragma unroll
    for (int o = 1; o < 32; o <<= 1) {
        int u = __shfl_up_sync(0xFFFFFFFFu, v, o);
        if (lane >= o) v += u;
    }
    if (lane == 31) ws[w] = v;
    __syncthreads();
    if (w == 0) {
        int s = ws[lane];
#pragma unroll
        for (int o = 1; o < 32; o <<= 1) {
            int u = __shfl_up_sync(0xFFFFFFFFu, s, o);
            if (lane >= o) s += u;
        }
        ws[lane] = s;
    }
    __syncthreads();
    return v + ((w > 0) ? ws[w - 1] : 0);
}

// Fused decoupled-lookback scan: counts -> offsets (+cursor, +total).
__global__ __launch_bounds__(SCAN_B)
void scan_fused_kernel(int n, int nblk)
{
    const int b = blockIdx.x;
    const int t = threadIdx.x;
    const int i = b * SCAN_B + t;
    const int v = (i < n) ? g_counts[i] : 0;
    const int incl = block_scan_incl(v);

    __shared__ int s_base;
    __shared__ int s_pred[128];

    if (t == SCAN_B - 1)
        atomicExch(&g_pub[b], incl | 0x40000000);

    if (t < 128) {
        int val = 0;
        if (t < b) {
            int s;
            do { s = *(volatile int*)&g_pub[t]; } while (!(s & 0x40000000));
            val = s & 0x3FFFFFFF;
        }
        s_pred[t] = val;
    }
    __syncthreads();
    if (t < 32) {
        int s = s_pred[t] + s_pred[t + 32] + s_pred[t + 64] + s_pred[t + 96];
#pragma unroll
        for (int o = 16; o; o >>= 1) s += __shfl_down_sync(0xFFFFFFFFu, s, o);
        if (t == 0) s_base = s;
    }
    __syncthreads();
    const int base = s_base;

    if (i < n) {
        const int o = base + incl - v;
        g_offsets[i] = o;
        g_cursor[i]  = o;
    }
    if (b == nblk - 1 && t == SCAN_B - 1)
        g_offsets[n] = base + incl;
}

__global__ void scatter_kernel(const int* __restrict__ erow,
                               const int* __restrict__ ecol,
                               const float* __restrict__ ew, int E)
{
    int e = blockIdx.x * blockDim.x + threadIdx.x;
    if (e < E) {
        int p = atomicAdd(&g_cursor[__ldcs(&erow[e])], 1);
        g_csr[p] = make_int2(__ldcs(&ecol[e]), __float_as_int(__ldcs(&ew[e])));
    }
}

// ---------------- aggregation: one warp per row, fp16 h gather -------------
// Lane handles cols 4*lane..4*lane+3: one uint2 (4 halves) per edge.
__global__ __launch_bounds__(256)
void agg_kernel(float* __restrict__ out, int N)
{
    const int wid  = (blockIdx.x * blockDim.x + threadIdx.x) >> 5;
    const int lane = threadIdx.x & 31;
    if (wid >= N) return;

    const int beg = g_offsets[wid];
    const int end = g_offsets[wid + 1];
    const uint2* __restrict__ h8 = (const uint2*)g_hh;   // 8B = 4 halves

    float4 a0 = make_float4(0.f, 0.f, 0.f, 0.f);
    float4 a1 = make_float4(0.f, 0.f, 0.f, 0.f);

    int e = beg;
    for (; e + 2 <= end; e += 2) {
        const int2 m0 = __ldcs(&g_csr[e]);
        const int2 m1 = __ldcs(&g_csr[e + 1]);
        const uint2 u0 = h8[(size_t)m0.x * 32 + lane];
        const uint2 u1 = h8[(size_t)m1.x * 32 + lane];
        const float w0 = __int_as_float(m0.y);
        const float w1 = __int_as_float(m1.y);
        const float2 v0a = __half22float2(*(const __half2*)&u0.x);
        const float2 v0b = __half22float2(*(const __half2*)&u0.y);
        const float2 v1a = __half22float2(*(const __half2*)&u1.x);
        const float2 v1b = __half22float2(*(const __half2*)&u1.y);
        a0.x = fmaf(w0, v0a.x, a0.x); a0.y = fmaf(w0, v0a.y, a0.y);
        a0.z = fmaf(w0, v0b.x, a0.z); a0.w = fmaf(w0, v0b.y, a0.w);
        a1.x = fmaf(w1, v1a.x, a1.x); a1.y = fmaf(w1, v1a.y, a1.y);
        a1.z = fmaf(w1, v1b.x, a1.z); a1.w = fmaf(w1, v1b.y, a1.w);
    }
    if (e < end) {
        const int2 m0 = __ldcs(&g_csr[e]);
        const uint2 u0 = h8[(size_t)m0.x * 32 + lane];
        const float w0 = __int_as_float(m0.y);
        const float2 v0a = __half22float2(*(const __half2*)&u0.x);
        const float2 v0b = __half22float2(*(const __half2*)&u0.y);
        a0.x = fmaf(w0, v0a.x, a0.x); a0.y = fmaf(w0, v0a.y, a0.y);
        a0.z = fmaf(w0, v0b.x, a0.z); a0.w = fmaf(w0, v0b.y, a0.w);
    }

    float4 r;
    r.x = fmaxf(a0.x + a1.x, 0.f);
    r.y = fmaxf(a0.y + a1.y, 0.f);
    r.z = fmaxf(a0.z + a1.z, 0.f);
    r.w = fmaxf(a0.w + a1.w, 0.f);
    __stcs(&((float4*)out)[(size_t)wid * 32 + lane], r);
}

// ---------------------------------------------------------------------------
extern "C" void kernel_launch(void* const* d_in, const int* in_sizes, int n_in,
                              void* d_out, int out_size)
{
    const float* x    = (const float*)d_in[0];
    const float* mask = (const float*)d_in[1];
    const float* W    = (const float*)d_in[2];
    const int*   erow = (const int*)d_in[3];
    const int*   ecol = (const int*)d_in[4];
    const float* ew   = (const float*)d_in[5];
    float* out = (float*)d_out;

    const int M = in_sizes[0] / D_IN;   // 100000
    const int E = in_sizes[3];          // 1600000
    const int nblk = (M + SCAN_B - 1) / SCAN_B;   // 98

    static cudaStream_t s_side = nullptr;
    static cudaEvent_t  s_fork = nullptr, s_join = nullptr;
    if (s_side == nullptr) {
        cudaStreamCreateWithFlags(&s_side, cudaStreamNonBlocking);
        cudaEventCreateWithFlags(&s_fork, cudaEventDisableTiming);
        cudaEventCreateWithFlags(&s_join, cudaEventDisableTiming);
    }

    // fork: side stream converts W then runs the tensor GEMM
    cudaEventRecord(s_fork, 0);
    cudaStreamWaitEvent(s_side, s_fork, 0);
    wconv_kernel<<<32, 256, 0, s_side>>>(W);
    gemm_mma_kernel<<<(M + 127) / 128, 256, 0, s_side>>>(x, mask, M);
    cudaEventRecord(s_join, s_side);

    // main stream: CSR build
    zero_kernel<<<(M + 256) / 256, 256>>>(M);
    hist_kernel<<<(E + 255) / 256, 256>>>(erow, E);
    scan_fused_kernel<<<nblk, SCAN_B>>>(M, nblk);
    scatter_kernel<<<(E + 255) / 256, 256>>>(erow, ecol, ew, E);

    // join, then aggregate
    cudaStreamWaitEvent(0, s_join, 0);
    agg_kernel<<<((size_t)M * 32 + 255) / 256, 256>>>(out, M);
}